// round 9
// baseline (speedup 1.0000x reference)
#include <cuda_runtime.h>
#include <cuda_bf16.h>
#include <cstdint>

// Problem constants
#define NN 16384          // points
#define CC 64             // input channels
#define KK 16             // neighbors
#define RR 4              // shuffle factor
#define CO 256            // C*R output channels of the MLP
#define SCHUNK 16         // column chunks for knn
#define JPC (NN / SCHUNK) // 1024 columns per chunk
#define TM 128            // rows per knn block (1 thread per row)

// -------- device scratch (no allocations allowed) --------
__device__ float g_sq[NN];
__device__ float g_cand_d[SCHUNK * KK * NN];   // [slot][row], 16.7 MB
__device__ int   g_cand_i[SCHUNK * KK * NN];   // 16.7 MB
__device__ int   g_nbr[NN * KK];
__device__ float g_u[NN * CO];                 // 16.7 MB
__device__ float g_v[NN * CO];                 // 16.7 MB

// -------- f32x2 packed helpers (sm_103a packed fp32 pipe) --------
__device__ __forceinline__ void ffma2(unsigned long long& d,
                                      unsigned long long a,
                                      unsigned long long b) {
    asm("fma.rn.f32x2 %0, %1, %2, %0;" : "+l"(d) : "l"(a), "l"(b));
}
__device__ __forceinline__ void fadd2(unsigned long long& d, unsigned long long a) {
    asm("add.rn.f32x2 %0, %0, %1;" : "+l"(d) : "l"(a));
}
__device__ __forceinline__ float unpack_sum(unsigned long long v) {
    unsigned lo, hi;
    asm("mov.b64 {%0, %1}, %2;" : "=r"(lo), "=r"(hi) : "l"(v));
    return __uint_as_float(lo) + __uint_as_float(hi);
}

#define FINF __int_as_float(0x7f800000)

// ---------------------------------------------------------------------------
// K1: squared row norms
// ---------------------------------------------------------------------------
__global__ void sq_kernel(const float* __restrict__ x) {
    int i = blockIdx.x * blockDim.x + threadIdx.x;
    if (i >= NN) return;
    const float4* p = reinterpret_cast<const float4*>(x) + i * (CC / 4);
    float s = 0.f;
#pragma unroll
    for (int q = 0; q < CC / 4; ++q) {
        float4 v = p[q];
        s = fmaf(v.x, v.x, s);
        s = fmaf(v.y, v.y, s);
        s = fmaf(v.z, v.z, s);
        s = fmaf(v.w, v.w, s);
    }
    g_sq[i] = s;
}

// ---------------------------------------------------------------------------
// K2: partial kNN. Block = (chunk, rowblock). Thread owns one row; the
// 128-column tile lives in smem; dot products run on the packed f32x2 pipe.
// ---------------------------------------------------------------------------
__global__ __launch_bounds__(TM, 4)
void knn_partial(const float* __restrict__ x) {
    const int chunk = blockIdx.x;          // 0..15
    const int row0  = blockIdx.y * TM;
    const int t     = threadIdx.x;         // 0..127
    const int i     = row0 + t;

    __shared__ float4 sx[128 * (CC / 4)];  // 128 cols x 64 floats = 32 KB
    __shared__ float  ssq[128];

    // x_i into registers as packed f32x2 pairs
    ulonglong2 xi[CC / 4];
    {
        const ulonglong2* p = reinterpret_cast<const ulonglong2*>(x) + i * (CC / 4);
#pragma unroll
        for (int q = 0; q < CC / 4; ++q) xi[q] = p[q];
    }
    const float sqi = g_sq[i];

    float dist[KK];
    int   idx[KK];
#pragma unroll
    for (int s = 0; s < KK; ++s) { dist[s] = FINF; idx[s] = -1; }
    float worst = FINF;

    const int j0 = chunk * JPC;
    for (int tile = 0; tile < JPC / 128; ++tile) {
        const int jt = j0 + tile * 128;
        __syncthreads();
        {   // cooperative tile load (coalesced 32 KB linear copy)
            const float4* src = reinterpret_cast<const float4*>(x) + jt * (CC / 4);
#pragma unroll
            for (int q = 0; q < 16; ++q) sx[q * 128 + t] = src[q * 128 + t];
            ssq[t] = g_sq[jt + t];
        }
        __syncthreads();

        const ulonglong2* sxl = reinterpret_cast<const ulonglong2*>(sx);
        for (int jj = 0; jj < 128; ++jj) {
            const ulonglong2* p = sxl + jj * (CC / 4);
            unsigned long long a0 = 0ull, a1 = 0ull, a2 = 0ull, a3 = 0ull;
#pragma unroll
            for (int q = 0; q < CC / 4; q += 2) {
                ulonglong2 w0 = p[q];
                ulonglong2 w1 = p[q + 1];
                ffma2(a0, w0.x, xi[q].x);
                ffma2(a1, w0.y, xi[q].y);
                ffma2(a2, w1.x, xi[q + 1].x);
                ffma2(a3, w1.y, xi[q + 1].y);
            }
            fadd2(a0, a1);
            fadd2(a2, a3);
            fadd2(a0, a2);
            float dot = unpack_sum(a0);
            float d = fmaf(-2.f, dot, sqi + ssq[jj]);
            int j = jt + jj;
            if (d < worst && j != i) {          // rare branch (~82 hits/thread)
                float cd = d; int ci = j;
#pragma unroll
                for (int s = 0; s < KK; ++s) {
                    if (cd < dist[s]) {
                        float td = dist[s]; dist[s] = cd; cd = td;
                        int   ti = idx[s];  idx[s]  = ci; ci = ti;
                    }
                }
                worst = dist[KK - 1];
            }
        }
    }

    // column-major candidate store: coalesced across threads
#pragma unroll
    for (int s = 0; s < KK; ++s) {
        g_cand_d[(chunk * KK + s) * NN + i] = dist[s];
        g_cand_i[(chunk * KK + s) * NN + i] = idx[s];
    }
}

// ---------------------------------------------------------------------------
// K3: merge per-chunk candidates -> global top-16 indices
// ---------------------------------------------------------------------------
__global__ void knn_merge() {
    int i = blockIdx.x * blockDim.x + threadIdx.x;
    if (i >= NN) return;
    float dist[KK];
    int   idx[KK];
#pragma unroll
    for (int s = 0; s < KK; ++s) { dist[s] = FINF; idx[s] = -1; }
    float worst = FINF;
    for (int k = 0; k < SCHUNK * KK; ++k) {
        float d = g_cand_d[k * NN + i];      // coalesced
        if (d < worst) {
            int j = g_cand_i[k * NN + i];
            if (j < 0) continue;             // never true (>=16 finite cands) — safety
            float cd = d; int ci = j;
#pragma unroll
            for (int s = 0; s < KK; ++s) {
                if (cd < dist[s]) {
                    float td = dist[s]; dist[s] = cd; cd = td;
                    int   ti = idx[s];  idx[s]  = ci; ci = ti;
                }
            }
            worst = dist[KK - 1];
        }
    }
#pragma unroll
    for (int s = 0; s < KK; ++s) g_nbr[i * KK + s] = idx[s];
}

// ---------------------------------------------------------------------------
// K4: u = x @ (W_top - W_bot) + b ;  v = x @ W_bot
// block: 128 threads <-> 128 cols (blockIdx.y selects half), 16 rows/block
// ---------------------------------------------------------------------------
__global__ __launch_bounds__(128)
void proj_kernel(const float* __restrict__ x, const float* __restrict__ W,
                 const float* __restrict__ b) {
    __shared__ float xs[16 * CC];   // 4 KB
    const int r0 = blockIdx.x * 16;
    const int c  = blockIdx.y * 128 + threadIdx.x;

    {   // load 16 rows of x
        const float4* src = reinterpret_cast<const float4*>(x) + r0 * (CC / 4);
        float4* dst = reinterpret_cast<float4*>(xs);
#pragma unroll
        for (int q = threadIdx.x; q < 16 * (CC / 4); q += 128) dst[q] = src[q];
    }
    __syncthreads();

    float au[16], av[16];
    const float bc = b[c];
#pragma unroll
    for (int r = 0; r < 16; ++r) { au[r] = bc; av[r] = 0.f; }

    for (int k = 0; k < CC; ++k) {
        float w1 = W[k * CO + c];          // W_top[k][c]   (coalesced)
        float w2 = W[(CC + k) * CO + c];   // W_bot[k][c]
        float wd = w1 - w2;
#pragma unroll
        for (int r = 0; r < 16; ++r) {
            float xv = xs[r * CC + k];     // smem broadcast
            au[r] = fmaf(xv, wd, au[r]);
            av[r] = fmaf(xv, w2, av[r]);
        }
    }
#pragma unroll
    for (int r = 0; r < 16; ++r) {
        g_u[(r0 + r) * CO + c] = au[r];
        g_v[(r0 + r) * CO + c] = av[r];
    }
}

// ---------------------------------------------------------------------------
// K5: out_i = max_j relu(u_i + v_{nbr_j}) then channel-shuffle store.
// One warp per point; v rows come from L2 (16.7 MB resident).
// ---------------------------------------------------------------------------
__global__ __launch_bounds__(256)
void gather_max(float* __restrict__ y) {
    const int gwarp = (blockIdx.x * blockDim.x + threadIdx.x) >> 5;
    const int lane  = threadIdx.x & 31;
    const int wl    = threadIdx.x >> 5;
    if (gwarp >= NN) return;
    const int i = gwarp;

    __shared__ float st[8][CO];   // 8 KB per block

    const float4* U = reinterpret_cast<const float4*>(g_u) + i * (CO / 4);
    float4 ua = U[lane * 2 + 0];
    float4 ub = U[lane * 2 + 1];

    float4 ma = make_float4(-FINF, -FINF, -FINF, -FINF);
    float4 mb = ma;

    int nbr = (lane < KK) ? g_nbr[i * KK + lane] : 0;
#pragma unroll
    for (int s = 0; s < KK; ++s) {
        int j = __shfl_sync(0xffffffffu, nbr, s);
        const float4* V = reinterpret_cast<const float4*>(g_v) + j * (CO / 4);
        float4 va = V[lane * 2 + 0];
        float4 vb = V[lane * 2 + 1];
        ma.x = fmaxf(ma.x, ua.x + va.x); ma.y = fmaxf(ma.y, ua.y + va.y);
        ma.z = fmaxf(ma.z, ua.z + va.z); ma.w = fmaxf(ma.w, ua.w + va.w);
        mb.x = fmaxf(mb.x, ub.x + vb.x); mb.y = fmaxf(mb.y, ub.y + vb.y);
        mb.z = fmaxf(mb.z, ub.z + vb.z); mb.w = fmaxf(mb.w, ub.w + vb.w);
    }

    // relu(max) == max(relu) by monotonicity
    float out[8];
    out[0] = fmaxf(ma.x, 0.f); out[1] = fmaxf(ma.y, 0.f);
    out[2] = fmaxf(ma.z, 0.f); out[3] = fmaxf(ma.w, 0.f);
    out[4] = fmaxf(mb.x, 0.f); out[5] = fmaxf(mb.y, 0.f);
    out[6] = fmaxf(mb.z, 0.f); out[7] = fmaxf(mb.w, 0.f);

    // stage with smem permutation: y[(i*4+r)*64 + c] = out_i[c*4 + r]
#pragma unroll
    for (int tt = 0; tt < 8; ++tt) {
        int col = lane * 8 + tt;        // channel index (c*4 + r)
        int c = col >> 2;
        int r = col & 3;
        st[wl][r * CC + c] = out[tt];
    }
    __syncwarp();

    float4* dst = reinterpret_cast<float4*>(y) + i * (CO / 4);
    const float4* src = reinterpret_cast<const float4*>(st[wl]);
    dst[lane * 2 + 0] = src[lane * 2 + 0];
    dst[lane * 2 + 1] = src[lane * 2 + 1];
}

// ---------------------------------------------------------------------------
extern "C" void kernel_launch(void* const* d_in, const int* in_sizes, int n_in,
                              void* d_out, int out_size) {
    const float* x = (const float*)d_in[0];   // (16384, 64)
    const float* W = (const float*)d_in[1];   // (128, 256)
    const float* b = (const float*)d_in[2];   // (256,)
    float* y = (float*)d_out;                 // (65536, 64)

    sq_kernel<<<NN / 256, 256>>>(x);

    dim3 g2(SCHUNK, NN / TM);                 // 16 x 128 = 2048 blocks
    knn_partial<<<g2, TM>>>(x);

    knn_merge<<<NN / 256, 256>>>();

    dim3 g4(NN / 16, 2);                      // 1024 x 2
    proj_kernel<<<g4, 128>>>(x, W, b);

    gather_max<<<(NN * 32) / 256, 256>>>(y);
}

// round 14
// speedup vs baseline: 1.6803x; 1.6803x over previous
#include <cuda_runtime.h>
#include <cuda_bf16.h>
#include <cstdint>

// Problem constants
#define NN 16384          // points
#define CC 64             // input channels
#define KK 16             // neighbors
#define CO 256            // C*R output channels
#define CH 2              // column chunks for knn
#define CPC (NN / CH)     // 8192 columns per chunk
#define TPT 128           // tile size (M = N = 128, K = 64)
#define TPC (CPC / TPT)   // 64 column tiles per chunk
#define NCAND 64          // candidates per row (CH * 2 halves * KK)

// smem layout (bytes) inside dynamic smem
#define ROWA 9            // uint4 per padded bf16 row (144 B)
#define ROWD 132          // floats per padded sD row
#define SM_A 0
#define SM_B (SM_A + TPT * ROWA * 16)              // 18432
#define SM_D (SM_B + TPT * ROWA * 16)              // 36864
#define SM_Q (SM_D + TPT * ROWD * 4)               // 104448
#define SMEM_BYTES (SM_Q + TPT * 4)                // 104960

// -------- device scratch (no allocations allowed) --------
__device__ float g_sq[NN];
__device__ __align__(16) __nv_bfloat16 g_xb[NN * CC];   // bf16 copy of x (2 MB)
__device__ __align__(16) int g_cand_i[NN * NCAND];      // 4 MB, row-major [i][64]
__device__ int   g_nbr[NN * KK];
__device__ float g_u[NN * CO];
__device__ float g_v[NN * CO];

#define FINF __int_as_float(0x7f800000)

// ---------------- warp-MMA helpers (compute_103-safe) ----------------
__device__ __forceinline__ uint32_t smem_u32(const void* p) {
    return (uint32_t)__cvta_generic_to_shared(p);
}
__device__ __forceinline__ void ldsm_x4(uint32_t* r, uint32_t addr) {
    asm volatile("ldmatrix.sync.aligned.m8n8.x4.shared.b16 {%0,%1,%2,%3}, [%4];"
                 : "=r"(r[0]), "=r"(r[1]), "=r"(r[2]), "=r"(r[3]) : "r"(addr));
}
__device__ __forceinline__ void mma16816(float* d, const uint32_t* a,
                                         uint32_t b0, uint32_t b1) {
    asm volatile(
        "mma.sync.aligned.m16n8k16.row.col.f32.bf16.bf16.f32 "
        "{%0,%1,%2,%3}, {%4,%5,%6,%7}, {%8,%9}, {%0,%1,%2,%3};"
        : "+f"(d[0]), "+f"(d[1]), "+f"(d[2]), "+f"(d[3])
        : "r"(a[0]), "r"(a[1]), "r"(a[2]), "r"(a[3]), "r"(b0), "r"(b1));
}

// ---------------------------------------------------------------------------
// K1: per-row squared norm (fp32, exact) + bf16 conversion of x
// ---------------------------------------------------------------------------
__global__ void prep_kernel(const float* __restrict__ x) {
    int i = blockIdx.x * blockDim.x + threadIdx.x;
    if (i >= NN) return;
    const float4* p = reinterpret_cast<const float4*>(x) + i * (CC / 4);
    __nv_bfloat162* o = reinterpret_cast<__nv_bfloat162*>(g_xb) + i * (CC / 2);
    float s = 0.f;
#pragma unroll
    for (int q = 0; q < CC / 4; ++q) {
        float4 v = p[q];
        s = fmaf(v.x, v.x, s); s = fmaf(v.y, v.y, s);
        s = fmaf(v.z, v.z, s); s = fmaf(v.w, v.w, s);
        o[q * 2 + 0] = __floats2bfloat162_rn(v.x, v.y);
        o[q * 2 + 1] = __floats2bfloat162_rn(v.z, v.w);
    }
    g_sq[i] = s;
}

// ---------------------------------------------------------------------------
// K2: approximate kNN via bf16 HMMA (mma.sync). Block = (chunk, row-tile).
// 8 warps; warp w computes rows [16w,16w+16) of the 128-row tile.
// Per column tile: MMA -> sD staging -> 2-threads-per-row top-16 scan.
// ---------------------------------------------------------------------------
__global__ void __launch_bounds__(256)
knn_mma(const float* __restrict__ xdummy) {
    extern __shared__ __align__(16) char smem[];
    uint4*  sA4 = reinterpret_cast<uint4*>(smem + SM_A);
    uint4*  sB4 = reinterpret_cast<uint4*>(smem + SM_B);
    float*  sD  = reinterpret_cast<float*>(smem + SM_D);
    float*  ssq = reinterpret_cast<float*>(smem + SM_Q);

    const int h  = blockIdx.x;             // chunk 0..1
    const int rb = blockIdx.y;             // row tile 0..127
    const int t  = threadIdx.x;            // 0..255
    const int w  = t >> 5;                 // warp 0..7 -> m-tile
    const int l  = t & 31;

    // ---- load A tile (128 rows x 64 bf16, padded 144B rows) ----
    {
        const uint4* srcA = reinterpret_cast<const uint4*>(g_xb) + (size_t)rb * TPT * 8;
#pragma unroll
        for (int u = t; u < TPT * 8; u += 256) {
            int r = u >> 3, q = u & 7;
            sA4[r * ROWA + q] = srcA[u];
        }
    }
    __syncthreads();

    // ---- A fragments: once per block. 4 k-steps x 4 regs ----
    uint32_t af[4][4];
    {
        const uint32_t baseA = smem_u32(sA4);
        const int rsel = ((l >> 3) & 1) * 8 + (l & 7);       // row within 16
        const int bsel = (l >> 4) * 16;                      // +16B for k8-15
#pragma unroll
        for (int ks = 0; ks < 4; ++ks) {
            uint32_t addr = baseA + (uint32_t)((w * 16 + rsel) * 144 + ks * 32 + bsel);
            ldsm_x4(af[ks], addr);
        }
    }

    // ---- per-thread top-16 state (2 threads per row: row = t&127, half = t>>7)
    const int row  = t & 127;
    const int half = t >> 7;
    const int i    = rb * TPT + row;

    float dist[KK];
    int   idx[KK];
#pragma unroll
    for (int s = 0; s < KK; ++s) { dist[s] = FINF; idx[s] = -1; }
    float worst = FINF;

    const uint32_t baseB = smem_u32(sB4);
    const int rselB = ((l >> 3) & 1) * 8 + (l & 7);
    const int bselB = (l >> 4) * 16;
    const int g  = l >> 2;      // acc row group
    const int tg = l & 3;       // acc col pair

    const int c00 = h * CPC;
    for (int tt = 0; tt < TPC; ++tt) {
        const int c0 = c00 + tt * TPT;

        __syncthreads();   // previous scan done (sB/ssq reusable)
        {   // load B tile + norms
            const uint4* srcB = reinterpret_cast<const uint4*>(g_xb) + (size_t)c0 * 8;
#pragma unroll
            for (int u = t; u < TPT * 8; u += 256) {
                int r = u >> 3, q = u & 7;
                sB4[r * ROWA + q] = srcB[u];
            }
            if (t < TPT) ssq[t] = g_sq[c0 + t];
        }
        __syncthreads();

        // ---- MMA: 128 cols in 4 quarters of 32 ----
#pragma unroll
        for (int nq = 0; nq < 4; ++nq) {
            float acc[4][4];
#pragma unroll
            for (int n8 = 0; n8 < 4; ++n8)
#pragma unroll
                for (int e = 0; e < 4; ++e) acc[n8][e] = 0.f;

#pragma unroll
            for (int ks = 0; ks < 4; ++ks) {
#pragma unroll
                for (int p = 0; p < 2; ++p) {          // n8 pairs
                    uint32_t br[4];
                    uint32_t addr = baseB +
                        (uint32_t)((nq * 32 + p * 16 + rselB) * 144 + ks * 32 + bselB);
                    ldsm_x4(br, addr);
                    mma16816(acc[p * 2 + 0], af[ks], br[0], br[2]);
                    mma16816(acc[p * 2 + 1], af[ks], br[1], br[3]);
                }
            }
            // stage quarter to sD (float2, rows w*16+g / +8)
#pragma unroll
            for (int n8 = 0; n8 < 4; ++n8) {
                int col = nq * 32 + n8 * 8 + tg * 2;
                float2* p0 = reinterpret_cast<float2*>(sD + (w * 16 + g) * ROWD + col);
                float2* p1 = reinterpret_cast<float2*>(sD + (w * 16 + g + 8) * ROWD + col);
                *p0 = make_float2(acc[n8][0], acc[n8][1]);
                *p1 = make_float2(acc[n8][2], acc[n8][3]);
            }
        }
        __syncthreads();

        // ---- scan: thread (row, half) scans 64 cols ----
        {
            const float4* drow = reinterpret_cast<const float4*>(sD + row * ROWD) + half * 16;
            const float4* sq4  = reinterpret_cast<const float4*>(ssq) + half * 16;
            const int jb0 = c0 + half * 64;
#pragma unroll 4
            for (int c4 = 0; c4 < 16; ++c4) {
                float4 dd = drow[c4];
                float4 qq = sq4[c4];
                float d0 = fmaf(-2.f, dd.x, qq.x);
                float d1 = fmaf(-2.f, dd.y, qq.y);
                float d2 = fmaf(-2.f, dd.z, qq.z);
                float d3 = fmaf(-2.f, dd.w, qq.w);
                float mn = fminf(fminf(d0, d1), fminf(d2, d3));
                if (mn < worst) {                       // rare
                    int jb = jb0 + c4 * 4;
                    float dv[4] = {d0, d1, d2, d3};
#pragma unroll
                    for (int e = 0; e < 4; ++e) {
                        int j = jb + e;
                        if (dv[e] < worst && j != i) {
                            float cd = dv[e]; int ci = j;
#pragma unroll
                            for (int s = 0; s < KK; ++s) {
                                if (cd < dist[s]) {
                                    float td = dist[s]; dist[s] = cd; cd = td;
                                    int   ti = idx[s];  idx[s]  = ci; ci = ti;
                                }
                            }
                            worst = dist[KK - 1];
                        }
                    }
                }
            }
        }
    }

    // ---- store 16 candidates: g_cand_i[i][ (h*2+half)*16 + s ], int4 x4 ----
    {
        int4* dst = reinterpret_cast<int4*>(&g_cand_i[(size_t)i * NCAND + (h * 2 + half) * KK]);
#pragma unroll
        for (int q = 0; q < 4; ++q)
            dst[q] = make_int4(idx[q * 4 + 0], idx[q * 4 + 1], idx[q * 4 + 2], idx[q * 4 + 3]);
    }
}

// ---------------------------------------------------------------------------
// K3: exact fp32 re-rank of the 64 candidates per row -> true top-16 set.
// One warp per row; each lane owns 2 candidates; shuffle all-pairs ranking.
// ---------------------------------------------------------------------------
__device__ __forceinline__ int dless(float a, int ja, float b, int jb) {
    return (a < b) || (a == b && ja < jb);
}
__global__ void __launch_bounds__(256) rerank_kernel(const float* __restrict__ x) {
    const int gw   = (blockIdx.x * blockDim.x + threadIdx.x) >> 5;
    const int lane = threadIdx.x & 31;
    if (gw >= NN) return;
    const int i = gw;
    const int j1 = g_cand_i[(size_t)i * NCAND + lane];
    const int j2 = g_cand_i[(size_t)i * NCAND + 32 + lane];

    const float4* xi = reinterpret_cast<const float4*>(x) + i * (CC / 4);
    const float4* xa = reinterpret_cast<const float4*>(x) + j1 * (CC / 4);
    const float4* xb = reinterpret_cast<const float4*>(x) + j2 * (CC / 4);
    float dot1 = 0.f, dot2 = 0.f;
#pragma unroll
    for (int q = 0; q < CC / 4; ++q) {
        float4 a = xi[q];                 // uniform -> L1 broadcast
        float4 v1 = xa[q];
        float4 v2 = xb[q];
        dot1 = fmaf(a.x, v1.x, dot1); dot1 = fmaf(a.y, v1.y, dot1);
        dot1 = fmaf(a.z, v1.z, dot1); dot1 = fmaf(a.w, v1.w, dot1);
        dot2 = fmaf(a.x, v2.x, dot2); dot2 = fmaf(a.y, v2.y, dot2);
        dot2 = fmaf(a.z, v2.z, dot2); dot2 = fmaf(a.w, v2.w, dot2);
    }
    float d1 = fmaf(-2.f, dot1, g_sq[j1]);   // sq_i common constant, dropped
    float d2 = fmaf(-2.f, dot2, g_sq[j2]);

    int rank1 = 0, rank2 = 0;
#pragma unroll
    for (int m = 0; m < 32; ++m) {
        float dm1 = __shfl_sync(0xffffffffu, d1, m);
        int   jm1 = __shfl_sync(0xffffffffu, j1, m);
        float dm2 = __shfl_sync(0xffffffffu, d2, m);
        int   jm2 = __shfl_sync(0xffffffffu, j2, m);
        rank1 += dless(dm1, jm1, d1, j1) + dless(dm2, jm2, d1, j1);
        rank2 += dless(dm1, jm1, d2, j2) + dless(dm2, jm2, d2, j2);
    }
    if (rank1 < KK) g_nbr[i * KK + rank1] = j1;
    if (rank2 < KK) g_nbr[i * KK + rank2] = j2;
}

// ---------------------------------------------------------------------------
// K4: u = x @ (W_top - W_bot) + b ;  v = x @ W_bot   (unchanged, known-good)
// ---------------------------------------------------------------------------
__global__ __launch_bounds__(128)
void proj_kernel(const float* __restrict__ x, const float* __restrict__ W,
                 const float* __restrict__ b) {
    __shared__ float xs[16 * CC];
    const int r0 = blockIdx.x * 16;
    const int c  = blockIdx.y * 128 + threadIdx.x;

    {
        const float4* src = reinterpret_cast<const float4*>(x) + r0 * (CC / 4);
        float4* dst = reinterpret_cast<float4*>(xs);
#pragma unroll
        for (int q = threadIdx.x; q < 16 * (CC / 4); q += 128) dst[q] = src[q];
    }
    __syncthreads();

    float au[16], av[16];
    const float bc = b[c];
#pragma unroll
    for (int r = 0; r < 16; ++r) { au[r] = bc; av[r] = 0.f; }

    for (int k = 0; k < CC; ++k) {
        float w1 = W[k * CO + c];
        float w2 = W[(CC + k) * CO + c];
        float wd = w1 - w2;
#pragma unroll
        for (int r = 0; r < 16; ++r) {
            float xv = xs[r * CC + k];
            au[r] = fmaf(xv, wd, au[r]);
            av[r] = fmaf(xv, w2, av[r]);
        }
    }
#pragma unroll
    for (int r = 0; r < 16; ++r) {
        g_u[(r0 + r) * CO + c] = au[r];
        g_v[(r0 + r) * CO + c] = av[r];
    }
}

// ---------------------------------------------------------------------------
// K5: out_i = max_j relu(u_i + v_{nbr_j}), channel-shuffle store (unchanged)
// ---------------------------------------------------------------------------
__global__ __launch_bounds__(256)
void gather_max(float* __restrict__ y) {
    const int gwarp = (blockIdx.x * blockDim.x + threadIdx.x) >> 5;
    const int lane  = threadIdx.x & 31;
    const int wl    = threadIdx.x >> 5;
    if (gwarp >= NN) return;
    const int i = gwarp;

    __shared__ float st[8][CO];

    const float4* U = reinterpret_cast<const float4*>(g_u) + i * (CO / 4);
    float4 ua = U[lane * 2 + 0];
    float4 ub = U[lane * 2 + 1];

    float4 ma = make_float4(-FINF, -FINF, -FINF, -FINF);
    float4 mb = ma;

    int nbr = (lane < KK) ? g_nbr[i * KK + lane] : 0;
#pragma unroll
    for (int s = 0; s < KK; ++s) {
        int j = __shfl_sync(0xffffffffu, nbr, s);
        const float4* V = reinterpret_cast<const float4*>(g_v) + j * (CO / 4);
        float4 va = V[lane * 2 + 0];
        float4 vb = V[lane * 2 + 1];
        ma.x = fmaxf(ma.x, ua.x + va.x); ma.y = fmaxf(ma.y, ua.y + va.y);
        ma.z = fmaxf(ma.z, ua.z + va.z); ma.w = fmaxf(ma.w, ua.w + va.w);
        mb.x = fmaxf(mb.x, ub.x + vb.x); mb.y = fmaxf(mb.y, ub.y + vb.y);
        mb.z = fmaxf(mb.z, ub.z + vb.z); mb.w = fmaxf(mb.w, ub.w + vb.w);
    }

    float out[8];
    out[0] = fmaxf(ma.x, 0.f); out[1] = fmaxf(ma.y, 0.f);
    out[2] = fmaxf(ma.z, 0.f); out[3] = fmaxf(ma.w, 0.f);
    out[4] = fmaxf(mb.x, 0.f); out[5] = fmaxf(mb.y, 0.f);
    out[6] = fmaxf(mb.z, 0.f); out[7] = fmaxf(mb.w, 0.f);

#pragma unroll
    for (int tt = 0; tt < 8; ++tt) {
        int col = lane * 8 + tt;
        int c = col >> 2;
        int r = col & 3;
        st[wl][r * CC + c] = out[tt];
    }
    __syncwarp();

    float4* dst = reinterpret_cast<float4*>(y) + i * (CO / 4);
    const float4* src = reinterpret_cast<const float4*>(st[wl]);
    dst[lane * 2 + 0] = src[lane * 2 + 0];
    dst[lane * 2 + 1] = src[lane * 2 + 1];
}

// ---------------------------------------------------------------------------
extern "C" void kernel_launch(void* const* d_in, const int* in_sizes, int n_in,
                              void* d_out, int out_size) {
    const float* x = (const float*)d_in[0];   // (16384, 64)
    const float* W = (const float*)d_in[1];   // (128, 256)
    const float* b = (const float*)d_in[2];   // (256,)
    float* y = (float*)d_out;                 // (65536, 64)

    static bool attr_done = false;
    if (!attr_done) {
        cudaFuncSetAttribute(knn_mma, cudaFuncAttributeMaxDynamicSharedMemorySize,
                             SMEM_BYTES);
        attr_done = true;
    }

    prep_kernel<<<NN / 256, 256>>>(x);

    dim3 g2(CH, NN / TPT);                    // 2 x 128 = 256 blocks
    knn_mma<<<g2, 256, SMEM_BYTES>>>(x);

    rerank_kernel<<<(NN * 32) / 256, 256>>>(x);

    dim3 g4(NN / 16, 2);
    proj_kernel<<<g4, 128>>>(x, W, b);

    gather_max<<<(NN * 32) / 256, 256>>>(y);
}

// round 17
// speedup vs baseline: 1.7010x; 1.0123x over previous
#include <cuda_runtime.h>
#include <cuda_bf16.h>
#include <cstdint>

// Problem constants
#define NN 16384          // points
#define CC 64             // input channels
#define KK 16             // neighbors
#define CO 256            // C*R output channels
#define CHUNKS 4          // column partitions for knn
#define CPCH (NN / CHUNKS)// 4096 columns per partition
#define NCAND 64          // candidates per row (CHUNKS * KK)
#define RPB 256           // rows per knn block (128 threads x 2 rows)

// -------- device scratch (no allocations allowed) --------
__device__ float g_sq[NN];                              // fp32 |x_i|^2 (rerank)
__device__ __align__(16) int g_q8[NN * 16];             // packed int8 rows (1 MB)
__device__ int   g_sq8[NN];                             // int |q_i|^2
__device__ __align__(16) int g_cand_i[NN * NCAND];      // 4 MB, row-major [i][64]
__device__ int   g_nbr[NN * KK];
__device__ float g_u[NN * CO];
__device__ float g_v[NN * CO];

#define FINF __int_as_float(0x7f800000)
#define QSCALE 30.0f
#define IMAXV 0x7fffffff

// ---------------------------------------------------------------------------
// K1: fp32 row norms + int8 quantization (+ int norms of quantized rows)
// ---------------------------------------------------------------------------
__global__ void prep_kernel(const float* __restrict__ x) {
    int i = blockIdx.x * blockDim.x + threadIdx.x;
    if (i >= NN) return;
    const float4* p = reinterpret_cast<const float4*>(x) + i * (CC / 4);
    int4* qo = reinterpret_cast<int4*>(g_q8) + i * 4;
    float s = 0.f;
    int   s8 = 0;
#pragma unroll
    for (int q = 0; q < 4; ++q) {       // 4 x int4, each packs 16 int8
        int w[4];
#pragma unroll
        for (int e = 0; e < 4; ++e) {
            float4 v = p[q * 4 + e];
            s = fmaf(v.x, v.x, s); s = fmaf(v.y, v.y, s);
            s = fmaf(v.z, v.z, s); s = fmaf(v.w, v.w, s);
            int q0 = max(-127, min(127, __float2int_rn(v.x * QSCALE)));
            int q1 = max(-127, min(127, __float2int_rn(v.y * QSCALE)));
            int q2 = max(-127, min(127, __float2int_rn(v.z * QSCALE)));
            int q3 = max(-127, min(127, __float2int_rn(v.w * QSCALE)));
            s8 += q0 * q0 + q1 * q1 + q2 * q2 + q3 * q3;
            w[e] = (q0 & 0xff) | ((q1 & 0xff) << 8) | ((q2 & 0xff) << 16) | (q3 << 24);
        }
        qo[q] = make_int4(w[0], w[1], w[2], w[3]);
    }
    g_sq[i] = s;
    g_sq8[i] = s8;
}

// ---------------------------------------------------------------------------
// K2: approximate kNN via dp4a int8 dot products.
// Block = (partition, row-block). 128 threads, 2 rows per thread.
// Proxy distance d = |q_j|^2 - 2 q_i.q_j (int, exact in quantized space).
// Per-partition top-16 per row -> 64 candidates overall.
// ---------------------------------------------------------------------------
__global__ void __launch_bounds__(128)
knn_dp4a() {
    __shared__ int4 scq[128 * 4];      // 128 cols x 64 int8 = 8 KB
    __shared__ int  ssq[128];

    const int ch = blockIdx.x;                 // partition 0..3
    const int rb = blockIdx.y;                 // row block 0..63
    const int t  = threadIdx.x;                // 0..127
    const int i0 = rb * RPB + t;
    const int i1 = i0 + 128;

    // both rows' quantized vectors in registers
    int4 xa[4], xb[4];
    {
        const int4* p0 = reinterpret_cast<const int4*>(g_q8) + i0 * 4;
        const int4* p1 = reinterpret_cast<const int4*>(g_q8) + i1 * 4;
#pragma unroll
        for (int q = 0; q < 4; ++q) { xa[q] = p0[q]; xb[q] = p1[q]; }
    }

    int dist0[KK], idx0[KK], dist1[KK], idx1[KK];
#pragma unroll
    for (int s = 0; s < KK; ++s) {
        dist0[s] = IMAXV; idx0[s] = -1;
        dist1[s] = IMAXV; idx1[s] = -1;
    }
    int worst0 = IMAXV, worst1 = IMAXV;

    const int c00 = ch * CPCH;
    for (int tile = 0; tile < CPCH / 128; ++tile) {
        const int c0 = c00 + tile * 128;
        __syncthreads();
        {   // load 128-column tile (coalesced) + int norms
            const int4* src = reinterpret_cast<const int4*>(g_q8) + (size_t)c0 * 4;
#pragma unroll
            for (int q = 0; q < 4; ++q) scq[q * 128 + t] = src[q * 128 + t];
            ssq[t] = g_sq8[c0 + t];
        }
        __syncthreads();

        for (int jj = 0; jj < 128; ++jj) {
            int a0 = 0, a1 = 0, a2 = 0, a3 = 0;
            int b0 = 0, b1 = 0, b2 = 0, b3 = 0;
#pragma unroll
            for (int q = 0; q < 4; ++q) {
                int4 w = scq[jj * 4 + q];          // warp broadcast
                a0 = __dp4a(w.x, xa[q].x, a0);
                a1 = __dp4a(w.y, xa[q].y, a1);
                a2 = __dp4a(w.z, xa[q].z, a2);
                a3 = __dp4a(w.w, xa[q].w, a3);
                b0 = __dp4a(w.x, xb[q].x, b0);
                b1 = __dp4a(w.y, xb[q].y, b1);
                b2 = __dp4a(w.z, xb[q].z, b2);
                b3 = __dp4a(w.w, xb[q].w, b3);
            }
            const int j  = c0 + jj;
            const int sj = ssq[jj];
            int d0 = sj - 2 * ((a0 + a1) + (a2 + a3));
            int d1 = sj - 2 * ((b0 + b1) + (b2 + b3));

            if (d0 < worst0 && j != i0) {          // rare
                int cd = d0, ci = j;
#pragma unroll
                for (int s = 0; s < KK; ++s) {
                    if (cd < dist0[s]) {
                        int td = dist0[s]; dist0[s] = cd; cd = td;
                        int ti = idx0[s];  idx0[s]  = ci; ci = ti;
                    }
                }
                worst0 = dist0[KK - 1];
            }
            if (d1 < worst1 && j != i1) {          // rare
                int cd = d1, ci = j;
#pragma unroll
                for (int s = 0; s < KK; ++s) {
                    if (cd < dist1[s]) {
                        int td = dist1[s]; dist1[s] = cd; cd = td;
                        int ti = idx1[s];  idx1[s]  = ci; ci = ti;
                    }
                }
                worst1 = dist1[KK - 1];
            }
        }
    }

    {   // store 16 candidates per row for this partition (int4 x4, aligned)
        int4* dst0 = reinterpret_cast<int4*>(&g_cand_i[(size_t)i0 * NCAND + ch * KK]);
        int4* dst1 = reinterpret_cast<int4*>(&g_cand_i[(size_t)i1 * NCAND + ch * KK]);
#pragma unroll
        for (int q = 0; q < 4; ++q) {
            dst0[q] = make_int4(idx0[q*4+0], idx0[q*4+1], idx0[q*4+2], idx0[q*4+3]);
            dst1[q] = make_int4(idx1[q*4+0], idx1[q*4+1], idx1[q*4+2], idx1[q*4+3]);
        }
    }
}

// ---------------------------------------------------------------------------
// K3: exact fp32 re-rank of the 64 candidates per row -> true top-16 set.
// One warp per row; each lane owns 2 candidates; shuffle all-pairs ranking.
// ---------------------------------------------------------------------------
__device__ __forceinline__ int dless(float a, int ja, float b, int jb) {
    return (a < b) || (a == b && ja < jb);
}
__global__ void __launch_bounds__(256) rerank_kernel(const float* __restrict__ x) {
    const int gw   = (blockIdx.x * blockDim.x + threadIdx.x) >> 5;
    const int lane = threadIdx.x & 31;
    if (gw >= NN) return;
    const int i = gw;
    const int j1 = g_cand_i[(size_t)i * NCAND + lane];
    const int j2 = g_cand_i[(size_t)i * NCAND + 32 + lane];

    const float4* xi = reinterpret_cast<const float4*>(x) + i * (CC / 4);
    const float4* xa = reinterpret_cast<const float4*>(x) + j1 * (CC / 4);
    const float4* xb = reinterpret_cast<const float4*>(x) + j2 * (CC / 4);
    float dot1 = 0.f, dot2 = 0.f;
#pragma unroll
    for (int q = 0; q < CC / 4; ++q) {
        float4 a = xi[q];                 // uniform -> L1 broadcast
        float4 v1 = xa[q];
        float4 v2 = xb[q];
        dot1 = fmaf(a.x, v1.x, dot1); dot1 = fmaf(a.y, v1.y, dot1);
        dot1 = fmaf(a.z, v1.z, dot1); dot1 = fmaf(a.w, v1.w, dot1);
        dot2 = fmaf(a.x, v2.x, dot2); dot2 = fmaf(a.y, v2.y, dot2);
        dot2 = fmaf(a.z, v2.z, dot2); dot2 = fmaf(a.w, v2.w, dot2);
    }
    float d1 = fmaf(-2.f, dot1, g_sq[j1]);   // sq_i common constant, dropped
    float d2 = fmaf(-2.f, dot2, g_sq[j2]);

    int rank1 = 0, rank2 = 0;
#pragma unroll
    for (int m = 0; m < 32; ++m) {
        float dm1 = __shfl_sync(0xffffffffu, d1, m);
        int   jm1 = __shfl_sync(0xffffffffu, j1, m);
        float dm2 = __shfl_sync(0xffffffffu, d2, m);
        int   jm2 = __shfl_sync(0xffffffffu, j2, m);
        rank1 += dless(dm1, jm1, d1, j1) + dless(dm2, jm2, d1, j1);
        rank2 += dless(dm1, jm1, d2, j2) + dless(dm2, jm2, d2, j2);
    }
    if (rank1 < KK) g_nbr[i * KK + rank1] = j1;
    if (rank2 < KK) g_nbr[i * KK + rank2] = j2;
}

// ---------------------------------------------------------------------------
// K4: u = x @ (W_top - W_bot) + b ;  v = x @ W_bot   (unchanged, known-good)
// ---------------------------------------------------------------------------
__global__ __launch_bounds__(128)
void proj_kernel(const float* __restrict__ x, const float* __restrict__ W,
                 const float* __restrict__ b) {
    __shared__ float xs[16 * CC];
    const int r0 = blockIdx.x * 16;
    const int c  = blockIdx.y * 128 + threadIdx.x;

    {
        const float4* src = reinterpret_cast<const float4*>(x) + r0 * (CC / 4);
        float4* dst = reinterpret_cast<float4*>(xs);
#pragma unroll
        for (int q = threadIdx.x; q < 16 * (CC / 4); q += 128) dst[q] = src[q];
    }
    __syncthreads();

    float au[16], av[16];
    const float bc = b[c];
#pragma unroll
    for (int r = 0; r < 16; ++r) { au[r] = bc; av[r] = 0.f; }

    for (int k = 0; k < CC; ++k) {
        float w1 = W[k * CO + c];
        float w2 = W[(CC + k) * CO + c];
        float wd = w1 - w2;
#pragma unroll
        for (int r = 0; r < 16; ++r) {
            float xv = xs[r * CC + k];
            au[r] = fmaf(xv, wd, au[r]);
            av[r] = fmaf(xv, w2, av[r]);
        }
    }
#pragma unroll
    for (int r = 0; r < 16; ++r) {
        g_u[(r0 + r) * CO + c] = au[r];
        g_v[(r0 + r) * CO + c] = av[r];
    }
}

// ---------------------------------------------------------------------------
// K5: out_i = max_j relu(u_i + v_{nbr_j}), channel-shuffle store (unchanged)
// ---------------------------------------------------------------------------
__global__ __launch_bounds__(256)
void gather_max(float* __restrict__ y) {
    const int gwarp = (blockIdx.x * blockDim.x + threadIdx.x) >> 5;
    const int lane  = threadIdx.x & 31;
    const int wl    = threadIdx.x >> 5;
    if (gwarp >= NN) return;
    const int i = gwarp;

    __shared__ float st[8][CO];

    const float4* U = reinterpret_cast<const float4*>(g_u) + i * (CO / 4);
    float4 ua = U[lane * 2 + 0];
    float4 ub = U[lane * 2 + 1];

    float4 ma = make_float4(-FINF, -FINF, -FINF, -FINF);
    float4 mb = ma;

    int nbr = (lane < KK) ? g_nbr[i * KK + lane] : 0;
#pragma unroll
    for (int s = 0; s < KK; ++s) {
        int j = __shfl_sync(0xffffffffu, nbr, s);
        const float4* V = reinterpret_cast<const float4*>(g_v) + j * (CO / 4);
        float4 va = V[lane * 2 + 0];
        float4 vb = V[lane * 2 + 1];
        ma.x = fmaxf(ma.x, ua.x + va.x); ma.y = fmaxf(ma.y, ua.y + va.y);
        ma.z = fmaxf(ma.z, ua.z + va.z); ma.w = fmaxf(ma.w, ua.w + va.w);
        mb.x = fmaxf(mb.x, ub.x + vb.x); mb.y = fmaxf(mb.y, ub.y + vb.y);
        mb.z = fmaxf(mb.z, ub.z + vb.z); mb.w = fmaxf(mb.w, ub.w + vb.w);
    }

    float out[8];
    out[0] = fmaxf(ma.x, 0.f); out[1] = fmaxf(ma.y, 0.f);
    out[2] = fmaxf(ma.z, 0.f); out[3] = fmaxf(ma.w, 0.f);
    out[4] = fmaxf(mb.x, 0.f); out[5] = fmaxf(mb.y, 0.f);
    out[6] = fmaxf(mb.z, 0.f); out[7] = fmaxf(mb.w, 0.f);

#pragma unroll
    for (int tt = 0; tt < 8; ++tt) {
        int col = lane * 8 + tt;
        int c = col >> 2;
        int r = col & 3;
        st[wl][r * CC + c] = out[tt];
    }
    __syncwarp();

    float4* dst = reinterpret_cast<float4*>(y) + i * (CO / 4);
    const float4* src = reinterpret_cast<const float4*>(st[wl]);
    dst[lane * 2 + 0] = src[lane * 2 + 0];
    dst[lane * 2 + 1] = src[lane * 2 + 1];
}

// ---------------------------------------------------------------------------
extern "C" void kernel_launch(void* const* d_in, const int* in_sizes, int n_in,
                              void* d_out, int out_size) {
    const float* x = (const float*)d_in[0];   // (16384, 64)
    const float* W = (const float*)d_in[1];   // (128, 256)
    const float* b = (const float*)d_in[2];   // (256,)
    float* y = (float*)d_out;                 // (65536, 64)

    prep_kernel<<<NN / 256, 256>>>(x);

    dim3 g2(CHUNKS, NN / RPB);                // 4 x 64 = 256 blocks
    knn_dp4a<<<g2, 128>>>();

    rerank_kernel<<<(NN * 32) / 256, 256>>>(x);

    dim3 g4(NN / 16, 2);
    proj_kernel<<<g4, 128>>>(x, W, b);

    gather_max<<<(NN * 32) / 256, 256>>>(y);
}